// round 2
// baseline (speedup 1.0000x reference)
#include <cuda_runtime.h>
#include <cstdint>

#define N_NODES_MAX 100000
#define OUT_DIM 128
#define IN_DIM 256

// Scratch for H = X @ W^T + b  (51.2 MB, device global per harness rules)
__device__ float g_H[(size_t)N_NODES_MAX * OUT_DIM];

// ---------------------------------------------------------------------------
// GEMM: H[M,128] = X[M,256] @ W[128,256]^T + b[128]
// Block = 256 threads. Tile: BM=64 rows, BN=128 (full), BK=32.
// smem stored k-major: sX[k][r] (stride 68), sW[k][c] (stride 132).
// Per-thread microtile: 8 rows x 4 cols.
// ---------------------------------------------------------------------------
__global__ __launch_bounds__(256) void gcn_gemm_kernel(
    const float* __restrict__ X,
    const float* __restrict__ W,
    const float* __restrict__ bias,
    int M)
{
    __shared__ float sX[32 * 68];    // [k][r]
    __shared__ float sW[32 * 132];   // [k][c]

    const int tid = threadIdx.x;
    const int tx  = tid & 31;        // col group: cols tx*4 .. tx*4+3
    const int ty  = tid >> 5;        // row group: rows ty*8 .. ty*8+7
    const int rowBase = blockIdx.x * 64;

    float acc[8][4];
#pragma unroll
    for (int i = 0; i < 8; ++i)
#pragma unroll
        for (int j = 0; j < 4; ++j) acc[i][j] = 0.f;

    for (int k0 = 0; k0 < IN_DIM; k0 += 32) {
        // ---- load X tile: 64 rows x 32 k, transpose into sX[k][r] ----
#pragma unroll
        for (int it = 0; it < 2; ++it) {
            int idx = tid + it * 256;          // 0..511  (64 rows * 8 float4)
            int r   = idx >> 3;                // row-local 0..63
            int k4  = (idx & 7) << 2;          // k-local 0,4,..,28
            int row = rowBase + r;
            float4 v = make_float4(0.f, 0.f, 0.f, 0.f);
            if (row < M)
                v = *(const float4*)(X + (size_t)row * IN_DIM + k0 + k4);
            sX[(k4 + 0) * 68 + r] = v.x;
            sX[(k4 + 1) * 68 + r] = v.y;
            sX[(k4 + 2) * 68 + r] = v.z;
            sX[(k4 + 3) * 68 + r] = v.w;
        }
        // ---- load W tile: 128 cols x 32 k, transpose into sW[k][c] ----
#pragma unroll
        for (int it = 0; it < 4; ++it) {
            int idx = tid + it * 256;          // 0..1023 (128 cols * 8 float4)
            int c   = idx >> 3;                // 0..127
            int k4  = (idx & 7) << 2;
            float4 v = *(const float4*)(W + (size_t)c * IN_DIM + k0 + k4);
            sW[(k4 + 0) * 132 + c] = v.x;
            sW[(k4 + 1) * 132 + c] = v.y;
            sW[(k4 + 2) * 132 + c] = v.z;
            sW[(k4 + 3) * 132 + c] = v.w;
        }
        __syncthreads();

#pragma unroll
        for (int k = 0; k < 32; ++k) {
            float4 a0 = *(const float4*)&sX[k * 68 + ty * 8];
            float4 a1 = *(const float4*)&sX[k * 68 + ty * 8 + 4];
            float4 w4 = *(const float4*)&sW[k * 132 + tx * 4];
            float a[8] = {a0.x, a0.y, a0.z, a0.w, a1.x, a1.y, a1.z, a1.w};
#pragma unroll
            for (int i = 0; i < 8; ++i) {
                acc[i][0] = fmaf(a[i], w4.x, acc[i][0]);
                acc[i][1] = fmaf(a[i], w4.y, acc[i][1]);
                acc[i][2] = fmaf(a[i], w4.z, acc[i][2]);
                acc[i][3] = fmaf(a[i], w4.w, acc[i][3]);
            }
        }
        __syncthreads();
    }

    // ---- epilogue: add bias, store to g_H ----
    float4 bv = *(const float4*)(bias + tx * 4);
#pragma unroll
    for (int i = 0; i < 8; ++i) {
        int row = rowBase + ty * 8 + i;
        if (row < M) {
            float4 o;
            o.x = acc[i][0] + bv.x;
            o.y = acc[i][1] + bv.y;
            o.z = acc[i][2] + bv.z;
            o.w = acc[i][3] + bv.w;
            *(float4*)(g_H + (size_t)row * OUT_DIM + tx * 4) = o;
        }
    }
}

// ---------------------------------------------------------------------------
// Edge scatter: out[row] += val * H[col], one warp per edge.
// Each lane handles one float4 (32 lanes * 4 = 128 features).
// Edge indices are int32 (JAX silently downcasts int64 without x64 mode).
// ---------------------------------------------------------------------------
__global__ __launch_bounds__(256) void gcn_scatter_kernel(
    const int*   __restrict__ edge_row,
    const int*   __restrict__ edge_col,
    const float* __restrict__ edge_val,
    float*       __restrict__ out,
    int E)
{
    int warp = (int)((blockIdx.x * (unsigned)blockDim.x + threadIdx.x) >> 5);
    int lane = threadIdx.x & 31;
    if (warp >= E) return;

    int   r = __ldg(edge_row + warp);
    int   c = __ldg(edge_col + warp);
    float v = __ldg(edge_val + warp);

    float4 h = *(const float4*)(g_H + (size_t)c * OUT_DIM + lane * 4);
    float* o = out + (size_t)r * OUT_DIM + lane * 4;
    atomicAdd(o + 0, v * h.x);
    atomicAdd(o + 1, v * h.y);
    atomicAdd(o + 2, v * h.z);
    atomicAdd(o + 3, v * h.w);
}

// ---------------------------------------------------------------------------
// Launch. Input order (metadata): X, edge_row, edge_col, edge_val, W, b.
// ---------------------------------------------------------------------------
extern "C" void kernel_launch(void* const* d_in, const int* in_sizes, int n_in,
                              void* d_out, int out_size)
{
    const float* X  = (const float*)d_in[0];
    const int*   er = (const int*)d_in[1];
    const int*   ec = (const int*)d_in[2];
    const float* ev = (const float*)d_in[3];
    const float* W  = (const float*)d_in[4];
    const float* b  = (const float*)d_in[5];
    float*      out = (float*)d_out;

    const int M = in_sizes[0] / IN_DIM;   // 100000
    const int E = in_sizes[3];            // 1600000

    // out starts as pure segment_sum accumulator -> zero it
    cudaMemsetAsync(d_out, 0, (size_t)out_size * sizeof(float));

    // H = X @ W^T + b
    gcn_gemm_kernel<<<(M + 63) / 64, 256>>>(X, W, b, M);

    // scatter: one warp per edge, 8 warps per 256-thread block
    int blocks = (E + 7) / 8;
    gcn_scatter_kernel<<<blocks, 256>>>(er, ec, ev, out, E);
}

// round 3
// speedup vs baseline: 1.6254x; 1.6254x over previous
#include <cuda_runtime.h>
#include <cstdint>

#define N_NODES_MAX 100000
#define OUT_DIM 128
#define IN_DIM 256

// Scratch for H = X @ W^T + b  (51.2 MB, device global per harness rules)
__device__ float g_H[(size_t)N_NODES_MAX * OUT_DIM];

// packed f32x2 fma (sm_100+): d.lo=a.lo*b.lo+c.lo, d.hi=a.hi*b.hi+c.hi
__device__ __forceinline__ unsigned long long fma2(
    unsigned long long a, unsigned long long b, unsigned long long c)
{
    unsigned long long d;
    asm("fma.rn.f32x2 %0, %1, %2, %3;" : "=l"(d) : "l"(a), "l"(b), "l"(c));
    return d;
}

__device__ __forceinline__ unsigned long long dup2(float w)
{
    unsigned long long d;
    asm("mov.b64 %0, {%1, %1};" : "=l"(d) : "f"(w));
    return d;
}

// ---------------------------------------------------------------------------
// GEMM: H[M,128] = X[M,256] @ W[128,256]^T + b[128]
// Block = 256 threads. Tile: BM=64 rows, BN=128, BK=32.
// smem k-major: sX[k][r] (stride 68 -> 272B rows, 16B aligned), sW[k][c].
// Per-thread microtile: 8 rows x 4 cols, accumulated as 4x4 packed f32x2
// (row pairs). Inner loop: 2x LDS.128 (a-pairs) + 1x LDS.128 (w) +
// 4x mov.b64 dup (ALU pipe) + 16x fma.rn.f32x2 (FMA pipe).
// ---------------------------------------------------------------------------
__global__ __launch_bounds__(256) void gcn_gemm_kernel(
    const float* __restrict__ X,
    const float* __restrict__ W,
    const float* __restrict__ bias,
    int M)
{
    __shared__ float sX[32 * 68];    // [k][r]
    __shared__ float sW[32 * 132];   // [k][c]

    const int tid = threadIdx.x;
    const int tx  = tid & 31;        // cols tx*4 .. tx*4+3
    const int ty  = tid >> 5;        // rows ty*8 .. ty*8+7
    const int rowBase = blockIdx.x * 64;

    // acc2[i2][j]: row-pair i2 (rows ty*8+2*i2, +1), col tx*4+j. packed f32x2.
    unsigned long long acc2[4][4];
#pragma unroll
    for (int i = 0; i < 4; ++i)
#pragma unroll
        for (int j = 0; j < 4; ++j) acc2[i][j] = 0ull;

    for (int k0 = 0; k0 < IN_DIM; k0 += 32) {
        // ---- load X tile: 64 rows x 32 k, transpose into sX[k][r] ----
#pragma unroll
        for (int it = 0; it < 2; ++it) {
            int idx = tid + it * 256;          // 0..511
            int r   = idx >> 3;
            int k4  = (idx & 7) << 2;
            int row = rowBase + r;
            float4 v = make_float4(0.f, 0.f, 0.f, 0.f);
            if (row < M)
                v = *(const float4*)(X + (size_t)row * IN_DIM + k0 + k4);
            sX[(k4 + 0) * 68 + r] = v.x;
            sX[(k4 + 1) * 68 + r] = v.y;
            sX[(k4 + 2) * 68 + r] = v.z;
            sX[(k4 + 3) * 68 + r] = v.w;
        }
        // ---- load W tile: 128 cols x 32 k, transpose into sW[k][c] ----
#pragma unroll
        for (int it = 0; it < 4; ++it) {
            int idx = tid + it * 256;          // 0..1023
            int c   = idx >> 3;
            int k4  = (idx & 7) << 2;
            float4 v = *(const float4*)(W + (size_t)c * IN_DIM + k0 + k4);
            sW[(k4 + 0) * 132 + c] = v.x;
            sW[(k4 + 1) * 132 + c] = v.y;
            sW[(k4 + 2) * 132 + c] = v.z;
            sW[(k4 + 3) * 132 + c] = v.w;
        }
        __syncthreads();

#pragma unroll
        for (int k = 0; k < 32; ++k) {
            // a row-pairs: (r0,r1)(r2,r3)(r4,r5)(r6,r7) as packed f32x2
            ulonglong2 aLo = *(const ulonglong2*)&sX[k * 68 + ty * 8];
            ulonglong2 aHi = *(const ulonglong2*)&sX[k * 68 + ty * 8 + 4];
            float4 w4 = *(const float4*)&sW[k * 132 + tx * 4];
            unsigned long long a2[4] = {aLo.x, aLo.y, aHi.x, aHi.y};
            unsigned long long w2[4] = {dup2(w4.x), dup2(w4.y), dup2(w4.z), dup2(w4.w)};
#pragma unroll
            for (int i = 0; i < 4; ++i) {
                acc2[i][0] = fma2(a2[i], w2[0], acc2[i][0]);
                acc2[i][1] = fma2(a2[i], w2[1], acc2[i][1]);
                acc2[i][2] = fma2(a2[i], w2[2], acc2[i][2]);
                acc2[i][3] = fma2(a2[i], w2[3], acc2[i][3]);
            }
        }
        __syncthreads();
    }

    // ---- epilogue: unpack, add bias, store to g_H ----
    float4 bv = *(const float4*)(bias + tx * 4);
#pragma unroll
    for (int i2 = 0; i2 < 4; ++i2) {
        int row0 = rowBase + ty * 8 + 2 * i2;
        float4 lo, hi;
        lo.x = __uint_as_float((unsigned)acc2[i2][0]) + bv.x;
        lo.y = __uint_as_float((unsigned)acc2[i2][1]) + bv.y;
        lo.z = __uint_as_float((unsigned)acc2[i2][2]) + bv.z;
        lo.w = __uint_as_float((unsigned)acc2[i2][3]) + bv.w;
        hi.x = __uint_as_float((unsigned)(acc2[i2][0] >> 32)) + bv.x;
        hi.y = __uint_as_float((unsigned)(acc2[i2][1] >> 32)) + bv.y;
        hi.z = __uint_as_float((unsigned)(acc2[i2][2] >> 32)) + bv.z;
        hi.w = __uint_as_float((unsigned)(acc2[i2][3] >> 32)) + bv.w;
        if (row0 < M)
            *(float4*)(g_H + (size_t)row0 * OUT_DIM + tx * 4) = lo;
        if (row0 + 1 < M)
            *(float4*)(g_H + (size_t)(row0 + 1) * OUT_DIM + tx * 4) = hi;
    }
}

// ---------------------------------------------------------------------------
// Edge scatter: out[row] += val * H[col], one warp per edge.
// Each lane handles one float4; single vectorized reduction (RED.128)
// instead of 4 scalar atomics -> 4x fewer L1tex atomic wavefronts.
// ---------------------------------------------------------------------------
__global__ __launch_bounds__(256) void gcn_scatter_kernel(
    const int*   __restrict__ edge_row,
    const int*   __restrict__ edge_col,
    const float* __restrict__ edge_val,
    float*       __restrict__ out,
    int E)
{
    int warp = (int)((blockIdx.x * (unsigned)blockDim.x + threadIdx.x) >> 5);
    int lane = threadIdx.x & 31;
    if (warp >= E) return;

    int   r = __ldg(edge_row + warp);
    int   c = __ldg(edge_col + warp);
    float v = __ldg(edge_val + warp);

    float4 h = *(const float4*)(g_H + (size_t)c * OUT_DIM + lane * 4);
    float* o = out + (size_t)r * OUT_DIM + lane * 4;
    asm volatile("red.global.add.v4.f32 [%0], {%1, %2, %3, %4};"
                 :: "l"(o), "f"(v * h.x), "f"(v * h.y), "f"(v * h.z), "f"(v * h.w)
                 : "memory");
}

// ---------------------------------------------------------------------------
// Launch. Input order (metadata): X, edge_row, edge_col, edge_val, W, b.
// ---------------------------------------------------------------------------
extern "C" void kernel_launch(void* const* d_in, const int* in_sizes, int n_in,
                              void* d_out, int out_size)
{
    const float* X  = (const float*)d_in[0];
    const int*   er = (const int*)d_in[1];
    const int*   ec = (const int*)d_in[2];
    const float* ev = (const float*)d_in[3];
    const float* W  = (const float*)d_in[4];
    const float* b  = (const float*)d_in[5];
    float*      out = (float*)d_out;

    const int M = in_sizes[0] / IN_DIM;   // 100000
    const int E = in_sizes[3];            // 1600000

    cudaMemsetAsync(d_out, 0, (size_t)out_size * sizeof(float));

    gcn_gemm_kernel<<<(M + 63) / 64, 256>>>(X, W, b, M);

    int blocks = (E + 7) / 8;
    gcn_scatter_kernel<<<blocks, 256>>>(er, ec, ev, out, E);
}